// round 12
// baseline (speedup 1.0000x reference)
#include <cuda_runtime.h>
#include <cuda_bf16.h>
#include <math.h>
#include <stdint.h>

// Problem constants
#define BB   4
#define CINE 256
#define CIN  1024
#define CO   256
#define HW   16384        // H*W = 128*128
#define CQ   32
#define NPOS 16384.0f

// GEMM smem layout (bytes). A: [buf][half][128 rows][80B]. Stage: [buf][32][512B].
// B: [buf][half][32 rows][272B].
#define XSA   0
#define XSA_BUF  20480
#define XSA_HALF 10240
#define XST   40960
#define XST_BUF  16384
#define XSB   73728
#define XSB_BUF  17408
#define XSB_HALF 8704
#define XTOT_CONV 108544
#define XSSC  108544
#define XSSF  109568
#define XTOT_QKV 110592

// Scratch (device globals -- no runtime allocation allowed)
__device__ float g_x[(size_t)BB * CO * HW];   // raw conv output (pre-BN)
__device__ float g_v[(size_t)BB * CO * HW];   // V
__device__ float g_q[BB * CQ * HW];           // Q then Qn
__device__ float g_k[BB * CQ * HW];           // K then Kn
__device__ float g_mean[CO];
__device__ float g_invstd[CO];
__device__ float g_ksum[BB * CQ];
__device__ float g_vsum[BB * CO];
__device__ float g_matrix[BB * CQ * CO];
// pre-split weights (bf16 hi/lo)
__device__ __nv_bfloat16 g_wc_h[CO * CIN], g_wc_l[CO * CIN];
__device__ __nv_bfloat16 g_wq_h[384 * CO], g_wq_l[384 * CO];   // rows 320..383 zero

__device__ __forceinline__ float fixnum(float r) {
    if (isnan(r)) return 0.0f;
    if (isinf(r)) return r > 0.0f ? 1.0f : -1.0f;
    return r;
}

__device__ __forceinline__ uint32_t smem_u32(const void* p) {
    uint32_t a;
    asm("{ .reg .u64 t; cvta.to.shared.u64 t, %1; cvt.u32.u64 %0, t; }"
        : "=r"(a) : "l"(p));
    return a;
}

#define CP_ASYNC(dst, src) \
    asm volatile("cp.async.cg.shared.global [%0], [%1], 16;" :: "r"(dst), "l"(src))
#define CP_COMMIT() asm volatile("cp.async.commit_group;" ::: "memory")
#define CP_WAIT0()  asm volatile("cp.async.wait_group 0;" ::: "memory")

__device__ __forceinline__ void ldm_x4(uint32_t& r0, uint32_t& r1,
                                       uint32_t& r2, uint32_t& r3, uint32_t addr) {
    asm volatile("ldmatrix.sync.aligned.m8n8.x4.shared.b16 {%0,%1,%2,%3}, [%4];"
                 : "=r"(r0), "=r"(r1), "=r"(r2), "=r"(r3) : "r"(addr));
}
__device__ __forceinline__ void ldm_x4t(uint32_t& r0, uint32_t& r1,
                                        uint32_t& r2, uint32_t& r3, uint32_t addr) {
    asm volatile("ldmatrix.sync.aligned.m8n8.x4.trans.shared.b16 {%0,%1,%2,%3}, [%4];"
                 : "=r"(r0), "=r"(r1), "=r"(r2), "=r"(r3) : "r"(addr));
}

// hi/lo bf16 split of two floats, packed as bf16x2 (x -> low 16 bits)
__device__ __forceinline__ void split_pack(float x, float y, uint32_t& h, uint32_t& l) {
    __nv_bfloat162 hb = __floats2bfloat162_rn(x, y);
    h = *reinterpret_cast<uint32_t*>(&hb);
    float rx = x - __bfloat162float(hb.x);
    float ry = y - __bfloat162float(hb.y);
    __nv_bfloat162 lb = __floats2bfloat162_rn(rx, ry);
    l = *reinterpret_cast<uint32_t*>(&lb);
}

// m16n8k16 row.col bf16 MMA, f32 accumulate in-place
__device__ __forceinline__ void mma16816(float* c,
    uint32_t a0, uint32_t a1, uint32_t a2, uint32_t a3,
    uint32_t b0, uint32_t b1)
{
    asm volatile(
        "mma.sync.aligned.m16n8k16.row.col.f32.bf16.bf16.f32 "
        "{%0,%1,%2,%3}, {%4,%5,%6,%7}, {%8,%9}, {%0,%1,%2,%3};"
        : "+f"(c[0]), "+f"(c[1]), "+f"(c[2]), "+f"(c[3])
        : "r"(a0), "r"(a1), "r"(a2), "r"(a3), "r"(b0), "r"(b1));
}

// ---------------------------------------------------------------------------
__global__ void zero_kernel() {
    int tid = blockIdx.x * blockDim.x + threadIdx.x;
    int total = BB * CQ + BB * CQ * CO;
    for (int i = tid; i < total; i += gridDim.x * blockDim.x) {
        if (i < BB * CQ) g_ksum[i] = 0.0f;
        else g_matrix[i - BB * CQ] = 0.0f;
    }
}

// ---------------------------------------------------------------------------
// Pre-split all weights to bf16 hi/lo. total = 256*1024 + 384*256 = 360448 els.
__global__ __launch_bounds__(256) void convert_weights(
    const float* __restrict__ w,
    const float* __restrict__ wq, const float* __restrict__ wk,
    const float* __restrict__ wv)
{
    int idx = blockIdx.x * 256 + threadIdx.x;
    if (idx < CO * CIN) {
        float f = w[idx];
        __nv_bfloat16 h = __float2bfloat16_rn(f);
        g_wc_h[idx] = h;
        g_wc_l[idx] = __float2bfloat16_rn(f - __bfloat162float(h));
    } else {
        int j = idx - CO * CIN;
        if (j < 384 * CO) {
            int row = j >> 8, k = j & 255;
            float f = (row < 32)  ? wq[row * CO + k]
                    : (row < 64)  ? wk[(row - 32) * CO + k]
                    : (row < 320) ? wv[(row - 64) * CO + k] : 0.0f;
            __nv_bfloat16 h = __float2bfloat16_rn(f);
            g_wq_h[j] = h;
            g_wq_l[j] = __float2bfloat16_rn(f - __bfloat162float(h));
        }
    }
}

// ---------------------------------------------------------------------------
// conv 1x1: g_x[b,m,n] = sum_c w[m,c]*fcat[b,c,n]. CTA 128x128, k-chunk 32.
// A: bf16 pre-split, cp.async direct. B: fp32 stage -> elementwise split -> ldmatrix.trans
__global__ __launch_bounds__(256, 2) void conv_gemm_mma(
    const float* __restrict__ s5, const float* __restrict__ s4,
    const float* __restrict__ s3, const float* __restrict__ s2)
{
    extern __shared__ char smem[];
    const uint32_t sb = smem_u32(smem);

    const int t = threadIdx.x;
    const int wid = t >> 5, lane = t & 31;
    const int g = lane >> 2, tg = lane & 3;
    const int b = blockIdx.z, m0 = blockIdx.y * 128, n0 = blockIdx.x * 128;
    const int wm = (wid & 1) * 64, wn = (wid >> 1) * 32;

    uint32_t aA[4];
#pragma unroll
    for (int mt = 0; mt < 4; mt++)
        aA[mt] = sb + XSA + (uint32_t)((wm + mt * 16 + (lane & 15)) * 80 + (lane >> 4) * 16);
    uint32_t aB[2];
#pragma unroll
    for (int p = 0; p < 2; p++)
        aB[p] = sb + XSB + (uint32_t)((lane & 15) * 272 + (wn + p * 16 + (lane >> 4) * 8) * 2);

    float acc[4][4][4];
#pragma unroll
    for (int i = 0; i < 4; i++)
#pragma unroll
        for (int j = 0; j < 4; j++)
#pragma unroll
            for (int r = 0; r < 4; r++) acc[i][j][r] = 0.0f;

    auto issue = [&](int buf, int k0) {
#pragma unroll
        for (int i = 0; i < 4; i++) {        // A bf16: 1024 x 16B chunks
            int id = t + i * 256;
            int half = id >> 9, id2 = id & 511, row = id2 >> 2, cs = id2 & 3;
            const __nv_bfloat16* src = (half ? g_wc_l : g_wc_h)
                + (size_t)(m0 + row) * CIN + k0 + cs * 8;
            CP_ASYNC(sb + XSA + buf * XSA_BUF + half * XSA_HALF + row * 80 + cs * 16, src);
        }
        int blk = k0 >> 8;                    // B fp32 stage: 1024 x 16B chunks
        const float* srcp = (blk == 0 ? s5 : blk == 1 ? s4 : blk == 2 ? s3 : s2)
            + (size_t)(b * CINE + (k0 & 255)) * HW + n0;
#pragma unroll
        for (int i = 0; i < 4; i++) {
            int id = t + i * 256;
            int row = id >> 5, c = id & 31;
            CP_ASYNC(sb + XST + buf * XST_BUF + row * 512 + ((c + row) & 31) * 16,
                     srcp + (size_t)row * HW + c * 4);
        }
    };

    issue(0, 0); CP_COMMIT();
    const int NI = CIN / 32;
    for (int it = 0; it < NI; it++) {
        const int buf = it & 1;
        CP_WAIT0();
        __syncthreads();   // buf data visible to all; all prev-iter mma reads done
        if (it + 1 < NI) { issue(buf ^ 1, (it + 1) * 32); CP_COMMIT(); }

        // elementwise split B: stage[buf] -> sBh/sBl (rotated stage columns)
        {
            const int r = t & 31, q = t >> 5;
            const char* stg = smem + XST + buf * XST_BUF + r * 512;
            char* ph = smem + XSB + buf * XSB_BUF + r * 272 + q * 32;
            char* pl = ph + XSB_HALF;
#pragma unroll
            for (int cc = 0; cc < 4; cc++) {
                int c = 4 * q + cc;
                float4 v = *(const float4*)(stg + ((c + r) & 31) * 16);
                uint32_t h0, l0, h1, l1;
                split_pack(v.x, v.y, h0, l0);
                split_pack(v.z, v.w, h1, l1);
                *(uint32_t*)(ph + cc * 8 + 0) = h0; *(uint32_t*)(ph + cc * 8 + 4) = h1;
                *(uint32_t*)(pl + cc * 8 + 0) = l0; *(uint32_t*)(pl + cc * 8 + 4) = l1;
            }
        }
        __syncthreads();

        const uint32_t offA = buf * XSA_BUF, offB = buf * XSB_BUF;
#pragma unroll
        for (int ks = 0; ks < 2; ks++) {
            const uint32_t oA = offA + ks * 32, oB = offB + ks * 4352;
            uint32_t af[4][4], bh[4][2], bl[4][2];
            ldm_x4t(bh[0][0], bh[0][1], bh[1][0], bh[1][1], aB[0] + oB);
            ldm_x4t(bh[2][0], bh[2][1], bh[3][0], bh[3][1], aB[1] + oB);
#pragma unroll
            for (int mt = 0; mt < 4; mt++)
                ldm_x4(af[mt][0], af[mt][1], af[mt][2], af[mt][3], aA[mt] + oA);
#pragma unroll
            for (int mt = 0; mt < 4; mt++)
#pragma unroll
                for (int nt = 0; nt < 4; nt++)
                    mma16816(acc[mt][nt], af[mt][0], af[mt][1], af[mt][2], af[mt][3],
                             bh[nt][0], bh[nt][1]);
            ldm_x4t(bl[0][0], bl[0][1], bl[1][0], bl[1][1], aB[0] + oB + XSB_HALF);
            ldm_x4t(bl[2][0], bl[2][1], bl[3][0], bl[3][1], aB[1] + oB + XSB_HALF);
#pragma unroll
            for (int mt = 0; mt < 4; mt++)
#pragma unroll
                for (int nt = 0; nt < 4; nt++)
                    mma16816(acc[mt][nt], af[mt][0], af[mt][1], af[mt][2], af[mt][3],
                             bl[nt][0], bl[nt][1]);
#pragma unroll
            for (int mt = 0; mt < 4; mt++)
                ldm_x4(af[mt][0], af[mt][1], af[mt][2], af[mt][3], aA[mt] + oA + XSA_HALF);
#pragma unroll
            for (int mt = 0; mt < 4; mt++)
#pragma unroll
                for (int nt = 0; nt < 4; nt++)
                    mma16816(acc[mt][nt], af[mt][0], af[mt][1], af[mt][2], af[mt][3],
                             bh[nt][0], bh[nt][1]);
        }
    }

    // writeback
#pragma unroll
    for (int mt = 0; mt < 4; mt++) {
        int m = m0 + wm + mt * 16 + g;
        float* base = g_x + (size_t)(b * CO + m) * HW + n0 + wn + 2 * tg;
#pragma unroll
        for (int nt = 0; nt < 4; nt++) {
            float* p = base + nt * 8;
            *(float2*)p = make_float2(acc[mt][nt][0], acc[mt][nt][1]);
            *(float2*)(p + 8 * HW) = make_float2(acc[mt][nt][2], acc[mt][nt][3]);
        }
    }
}

// ---------------------------------------------------------------------------
// BN statistics over raw conv output: one block per channel
__global__ __launch_bounds__(512) void bn_stats() {
    const int co = blockIdx.x;
    const int tid = threadIdx.x;
    float s = 0.0f, ss = 0.0f;
    for (int b = 0; b < BB; b++) {
        const float* p = g_x + (size_t)(b * CO + co) * HW;
        for (int i = tid; i < HW; i += 512) {
            float v = p[i];
            s += v;
            ss += v * v;
        }
    }
    __shared__ float rs[512], rss[512];
    rs[tid] = s; rss[tid] = ss;
    __syncthreads();
    for (int off = 256; off > 0; off >>= 1) {
        if (tid < off) { rs[tid] += rs[tid + off]; rss[tid] += rss[tid + off]; }
        __syncthreads();
    }
    if (tid == 0) {
        const float cnt = (float)(BB * HW);
        float mean = rs[0] / cnt;
        float var  = rss[0] / cnt - mean * mean;
        g_mean[co]   = mean;
        g_invstd[co] = rsqrtf(var + 1e-5f);
    }
}

// ---------------------------------------------------------------------------
// QKV GEMM: same pipeline, BN+ReLU fused into the elementwise split.
// rows 0..31 = Q, 32..63 = K, 64..319 = V (padded weights handle 320..383).
__global__ __launch_bounds__(256, 2) void qkv_gemm_mma(
    const float* __restrict__ bq, const float* __restrict__ bk,
    const float* __restrict__ bv,
    const float* __restrict__ bn_gamma, const float* __restrict__ bn_beta)
{
    extern __shared__ char smem[];
    const uint32_t sb = smem_u32(smem);

    const int t = threadIdx.x;
    const int wid = t >> 5, lane = t & 31;
    const int g = lane >> 2, tg = lane & 3;
    const int b = blockIdx.z, m0 = blockIdx.y * 128, n0 = blockIdx.x * 128;
    const int wm = (wid & 1) * 64, wn = (wid >> 1) * 32;

    {   // BN scale/shift (one channel per thread)
        float sc = g_invstd[t] * bn_gamma[t];
        ((float*)(smem + XSSC))[t] = sc;
        ((float*)(smem + XSSF))[t] = bn_beta[t] - g_mean[t] * sc;
    }

    uint32_t aA[4];
#pragma unroll
    for (int mt = 0; mt < 4; mt++)
        aA[mt] = sb + XSA + (uint32_t)((wm + mt * 16 + (lane & 15)) * 80 + (lane >> 4) * 16);
    uint32_t aB[2];
#pragma unroll
    for (int p = 0; p < 2; p++)
        aB[p] = sb + XSB + (uint32_t)((lane & 15) * 272 + (wn + p * 16 + (lane >> 4) * 8) * 2);

    float acc[4][4][4];
#pragma unroll
    for (int i = 0; i < 4; i++)
#pragma unroll
        for (int j = 0; j < 4; j++)
#pragma unroll
            for (int r = 0; r < 4; r++) acc[i][j][r] = 0.0f;

    auto issue = [&](int buf, int k0) {
#pragma unroll
        for (int i = 0; i < 4; i++) {
            int id = t + i * 256;
            int half = id >> 9, id2 = id & 511, row = id2 >> 2, cs = id2 & 3;
            const __nv_bfloat16* src = (half ? g_wq_l : g_wq_h)
                + (size_t)(m0 + row) * CO + k0 + cs * 8;
            CP_ASYNC(sb + XSA + buf * XSA_BUF + half * XSA_HALF + row * 80 + cs * 16, src);
        }
        const float* srcp = g_x + (size_t)(b * CO + k0) * HW + n0;
#pragma unroll
        for (int i = 0; i < 4; i++) {
            int id = t + i * 256;
            int row = id >> 5, c = id & 31;
            CP_ASYNC(sb + XST + buf * XST_BUF + row * 512 + ((c + row) & 31) * 16,
                     srcp + (size_t)row * HW + c * 4);
        }
    };

    issue(0, 0); CP_COMMIT();
    const int NI = CO / 32;
    for (int it = 0; it < NI; it++) {
        const int buf = it & 1;
        CP_WAIT0();
        __syncthreads();   // buf data visible; all prev-iter mma reads done
        if (it + 1 < NI) { issue(buf ^ 1, (it + 1) * 32); CP_COMMIT(); }

        {   // BN + ReLU + split
            const int r = t & 31, q = t >> 5;
            const int ch = it * 32 + r;
            const float sc = ((const float*)(smem + XSSC))[ch];
            const float sf = ((const float*)(smem + XSSF))[ch];
            const char* stg = smem + XST + buf * XST_BUF + r * 512;
            char* ph = smem + XSB + buf * XSB_BUF + r * 272 + q * 32;
            char* pl = ph + XSB_HALF;
#pragma unroll
            for (int cc = 0; cc < 4; cc++) {
                int c = 4 * q + cc;
                float4 v = *(const float4*)(stg + ((c + r) & 31) * 16);
                v.x = fmaxf(v.x * sc + sf, 0.0f);
                v.y = fmaxf(v.y * sc + sf, 0.0f);
                v.z = fmaxf(v.z * sc + sf, 0.0f);
                v.w = fmaxf(v.w * sc + sf, 0.0f);
                uint32_t h0, l0, h1, l1;
                split_pack(v.x, v.y, h0, l0);
                split_pack(v.z, v.w, h1, l1);
                *(uint32_t*)(ph + cc * 8 + 0) = h0; *(uint32_t*)(ph + cc * 8 + 4) = h1;
                *(uint32_t*)(pl + cc * 8 + 0) = l0; *(uint32_t*)(pl + cc * 8 + 4) = l1;
            }
        }
        __syncthreads();

        const uint32_t offA = buf * XSA_BUF, offB = buf * XSB_BUF;
#pragma unroll
        for (int ks = 0; ks < 2; ks++) {
            const uint32_t oA = offA + ks * 32, oB = offB + ks * 4352;
            uint32_t af[4][4], bh[4][2], bl[4][2];
            ldm_x4t(bh[0][0], bh[0][1], bh[1][0], bh[1][1], aB[0] + oB);
            ldm_x4t(bh[2][0], bh[2][1], bh[3][0], bh[3][1], aB[1] + oB);
#pragma unroll
            for (int mt = 0; mt < 4; mt++)
                ldm_x4(af[mt][0], af[mt][1], af[mt][2], af[mt][3], aA[mt] + oA);
#pragma unroll
            for (int mt = 0; mt < 4; mt++)
#pragma unroll
                for (int nt = 0; nt < 4; nt++)
                    mma16816(acc[mt][nt], af[mt][0], af[mt][1], af[mt][2], af[mt][3],
                             bh[nt][0], bh[nt][1]);
            ldm_x4t(bl[0][0], bl[0][1], bl[1][0], bl[1][1], aB[0] + oB + XSB_HALF);
            ldm_x4t(bl[2][0], bl[2][1], bl[3][0], bl[3][1], aB[1] + oB + XSB_HALF);
#pragma unroll
            for (int mt = 0; mt < 4; mt++)
#pragma unroll
                for (int nt = 0; nt < 4; nt++)
                    mma16816(acc[mt][nt], af[mt][0], af[mt][1], af[mt][2], af[mt][3],
                             bl[nt][0], bl[nt][1]);
#pragma unroll
            for (int mt = 0; mt < 4; mt++)
                ldm_x4(af[mt][0], af[mt][1], af[mt][2], af[mt][3], aA[mt] + oA + XSA_HALF);
#pragma unroll
            for (int mt = 0; mt < 4; mt++)
#pragma unroll
                for (int nt = 0; nt < 4; nt++)
                    mma16816(acc[mt][nt], af[mt][0], af[mt][1], af[mt][2], af[mt][3],
                             bh[nt][0], bh[nt][1]);
        }
    }

    // writeback with bias + routing (rows mg and mg+8)
#pragma unroll
    for (int mt = 0; mt < 4; mt++) {
#pragma unroll
        for (int half = 0; half < 2; half++) {
            int mg = m0 + wm + mt * 16 + g + half * 8;
            if (mg >= 320) continue;
            float bias; float* dst;
            if (mg < 32)      { bias = bq[mg];      dst = g_q + (size_t)(b * CQ + mg) * HW; }
            else if (mg < 64) { bias = bk[mg - 32]; dst = g_k + (size_t)(b * CQ + mg - 32) * HW; }
            else              { bias = bv[mg - 64]; dst = g_v + (size_t)(b * CO + mg - 64) * HW; }
            dst += n0 + wn + 2 * tg;
#pragma unroll
            for (int nt = 0; nt < 4; nt++)
                *(float2*)(dst + nt * 8) = make_float2(acc[mt][nt][2 * half] + bias,
                                                       acc[mt][nt][2 * half + 1] + bias);
        }
    }
}

// ---------------------------------------------------------------------------
// L2-normalize Q and K over channels per position, accumulate Ksum
__global__ __launch_bounds__(256) void normalize_qk() {
    const int b = blockIdx.y;
    const int n = blockIdx.x * 256 + threadIdx.x;
    const int lane = threadIdx.x & 31;

    {
        float q[CQ];
        float s = 0.0f;
#pragma unroll
        for (int c = 0; c < CQ; c++) {
            q[c] = g_q[(size_t)(b * CQ + c) * HW + n];
            s += q[c] * q[c];
        }
        float sc = 1.0f / fmaxf(sqrtf(s), 1e-6f);
#pragma unroll
        for (int c = 0; c < CQ; c++)
            g_q[(size_t)(b * CQ + c) * HW + n] = q[c] * sc;
    }
    {
        float k[CQ];
        float s = 0.0f;
#pragma unroll
        for (int c = 0; c < CQ; c++) {
            k[c] = g_k[(size_t)(b * CQ + c) * HW + n];
            s += k[c] * k[c];
        }
        float sc = 1.0f / fmaxf(sqrtf(s), 1e-6f);
#pragma unroll
        for (int c = 0; c < CQ; c++) {
            float v = k[c] * sc;
            g_k[(size_t)(b * CQ + c) * HW + n] = v;
            float r = v;
#pragma unroll
            for (int off = 16; off > 0; off >>= 1)
                r += __shfl_down_sync(0xffffffffu, r, off);
            if (lane == 0) atomicAdd(&g_ksum[b * CQ + c], r);
        }
    }
}

// ---------------------------------------------------------------------------
__global__ __launch_bounds__(256) void vsum_kernel() {
    const int c = blockIdx.x;
    const int b = blockIdx.y;
    const int tid = threadIdx.x;
    const float* p = g_v + (size_t)(b * CO + c) * HW;
    float s = 0.0f;
    for (int i = tid; i < HW; i += 256) s += p[i];
    __shared__ float rs[256];
    rs[tid] = s;
    __syncthreads();
    for (int off = 128; off > 0; off >>= 1) {
        if (tid < off) rs[tid] += rs[tid + off];
        __syncthreads();
    }
    if (tid == 0) g_vsum[b * CO + c] = rs[0];
}

// ---------------------------------------------------------------------------
// matrix[b,q,c] = sum_n Kn[b,q,n] * V[b,c,n]  (split-K over n, atomic reduce)
__global__ __launch_bounds__(256) void matrix_kernel() {
    const int b   = blockIdx.z;
    const int c0  = blockIdx.y * 64;
    const int nb0 = blockIdx.x * 512;

    __shared__ float sK[CQ][65];
    __shared__ float sV[64][65];

    const int t  = threadIdx.x;
    const int c  = t & 63;
    const int qg = t >> 6;

    float acc[8];
#pragma unroll
    for (int i = 0; i < 8; i++) acc[i] = 0.0f;

    for (int nb = nb0; nb < nb0 + 512; nb += 64) {
#pragma unroll
        for (int i = 0; i < 8; i++) {
            int idx = t + i * 256;
            int q = idx >> 6, j = idx & 63;
            sK[q][j] = g_k[(size_t)(b * CQ + q) * HW + nb + j];
        }
#pragma unroll
        for (int i = 0; i < 16; i++) {
            int idx = t + i * 256;
            int cc = idx >> 6, j = idx & 63;
            sV[cc][j] = g_v[(size_t)(b * CO + c0 + cc) * HW + nb + j];
        }
        __syncthreads();
#pragma unroll 8
        for (int j = 0; j < 64; j++) {
            float vv = sV[c][j];
#pragma unroll
            for (int i = 0; i < 8; i++)
                acc[i] += sK[qg * 8 + i][j] * vv;
        }
        __syncthreads();
    }
#pragma unroll
    for (int i = 0; i < 8; i++)
        atomicAdd(&g_matrix[(size_t)(b * CQ + qg * 8 + i) * CO + c0 + c], acc[i]);
}

// ---------------------------------------------------------------------------
// Final: out = nan_to_num(gamma * (Vsum + Qn^T matrix) * tailor) + feat
// feat = relu(bn(g_x)) computed inline.
__global__ __launch_bounds__(128) void final_kernel(
    const float* __restrict__ gamma_p,
    const float* __restrict__ bn_gamma, const float* __restrict__ bn_beta,
    float* __restrict__ out)
{
    const int b = blockIdx.y;
    const int n = blockIdx.x * 128 + threadIdx.x;
    const int tid = threadIdx.x;

    __shared__ float sM[CQ][CO];   // 32 KB
    __shared__ float sVs[CO];
    __shared__ float sKs[CQ];
    __shared__ float sScale[CO];
    __shared__ float sShift[CO];

#pragma unroll
    for (int i = 0; i < 64; i++) {
        int idx = tid + i * 128;
        ((float*)sM)[idx] = g_matrix[(size_t)b * CQ * CO + idx];
    }
#pragma unroll
    for (int r = 0; r < 2; r++) {
        int c = tid + r * 128;
        sVs[c] = g_vsum[b * CO + c];
        float scale = g_invstd[c] * bn_gamma[c];
        sScale[c] = scale;
        sShift[c] = bn_beta[c] - g_mean[c] * scale;
    }
    if (tid < CQ) sKs[tid] = g_ksum[b * CQ + tid];
    __syncthreads();

    float qn[CQ];
    float e = 0.0f;
#pragma unroll
    for (int q = 0; q < CQ; q++) {
        qn[q] = g_q[(size_t)(b * CQ + q) * HW + n];
        e += qn[q] * sKs[q];
    }
    const float tailor = 1.0f / fmaxf(NPOS + e, 1e-6f);
    const float gm = *gamma_p;

    for (int c0 = 0; c0 < CO; c0 += 4) {
        float4 a = *(const float4*)&sVs[c0];
#pragma unroll
        for (int q = 0; q < CQ; q++) {
            float4 m4 = *(const float4*)&sM[q][c0];
            a.x += qn[q] * m4.x;
            a.y += qn[q] * m4.y;
            a.z += qn[q] * m4.z;
            a.w += qn[q] * m4.w;
        }
        float r0 = fixnum(gm * a.x * tailor);
        float r1 = fixnum(gm * a.y * tailor);
        float r2 = fixnum(gm * a.z * tailor);
        float r3 = fixnum(gm * a.w * tailor);
        size_t base = (size_t)(b * CO + c0) * HW + n;
        float f0 = fmaxf(g_x[base + 0 * HW] * sScale[c0 + 0] + sShift[c0 + 0], 0.0f);
        float f1 = fmaxf(g_x[base + 1 * HW] * sScale[c0 + 1] + sShift[c0 + 1], 0.0f);
        float f2 = fmaxf(g_x[base + 2 * HW] * sScale[c0 + 2] + sShift[c0 + 2], 0.0f);
        float f3 = fmaxf(g_x[base + 3 * HW] * sScale[c0 + 3] + sShift[c0 + 3], 0.0f);
        out[base + 0 * HW] = r0 + f0;
        out[base + 1 * HW] = r1 + f1;
        out[base + 2 * HW] = r2 + f2;
        out[base + 3 * HW] = r3 + f3;
    }
}

// ---------------------------------------------------------------------------
extern "C" void kernel_launch(void* const* d_in, const int* in_sizes, int n_in,
                              void* d_out, int out_size)
{
    const float* s5 = (const float*)d_in[0];
    const float* s4 = (const float*)d_in[1];
    const float* s3 = (const float*)d_in[2];
    const float* s2 = (const float*)d_in[3];
    const float* w_conv   = (const float*)d_in[4];
    const float* bn_gamma = (const float*)d_in[5];
    const float* bn_beta  = (const float*)d_in[6];
    const float* wq = (const float*)d_in[7];
    const float* bq = (const float*)d_in[8];
    const float* wk = (const float*)d_in[9];
    const float* bk = (const float*)d_in[10];
    const float* wv = (const float*)d_in[11];
    const float* bv = (const float*)d_in[12];
    const float* gamma = (const float*)d_in[13];
    float* out = (float*)d_out;

    static int attr_done = 0;
    if (!attr_done) {
        cudaFuncSetAttribute(conv_gemm_mma, cudaFuncAttributeMaxDynamicSharedMemorySize, XTOT_QKV);
        cudaFuncSetAttribute(qkv_gemm_mma,  cudaFuncAttributeMaxDynamicSharedMemorySize, XTOT_QKV);
        attr_done = 1;
    }

    zero_kernel<<<64, 256>>>();
    convert_weights<<<1408, 256>>>(w_conv, wq, wk, wv);
    conv_gemm_mma<<<dim3(HW / 128, 2, BB), 256, XTOT_CONV>>>(s5, s4, s3, s2);
    bn_stats<<<CO, 512>>>();
    qkv_gemm_mma<<<dim3(HW / 128, 3, BB), 256, XTOT_QKV>>>(bq, bk, bv, bn_gamma, bn_beta);
    normalize_qk<<<dim3(HW / 256, BB), 256>>>();
    vsum_kernel<<<dim3(CO, BB), 256>>>();
    matrix_kernel<<<dim3(32, CO / 64, BB), 256>>>();
    final_kernel<<<dim3(HW / 128, BB), 128>>>(gamma, bn_gamma, bn_beta, out);
}

// round 13
// speedup vs baseline: 1.0213x; 1.0213x over previous
#include <cuda_runtime.h>
#include <cuda_bf16.h>
#include <math.h>
#include <stdint.h>

// Problem constants
#define BB   4
#define CINE 256
#define CIN  1024
#define CO   256
#define HW   16384        // H*W = 128*128
#define CQ   32
#define NPOS 16384.0f

// GEMM smem layout (bytes). A: [buf][half][128 rows][80B]. Stage: [buf][32][512B].
// B: [buf][half][32 rows][272B].
#define XSA   0
#define XSA_BUF  20480
#define XSA_HALF 10240
#define XST   40960
#define XST_BUF  16384
#define XSB   73728
#define XSB_BUF  17408
#define XSB_HALF 8704
#define XTOT_CONV 108544
#define XSSC  108544
#define XSSF  109568
#define XTOT_QKV 110592

// Scratch (device globals -- no runtime allocation allowed)
__device__ float g_x[(size_t)BB * CO * HW];   // raw conv output (pre-BN)
__device__ float g_v[(size_t)BB * CO * HW];   // V
__device__ float g_q[BB * CQ * HW];           // Q then Qn
__device__ float g_k[BB * CQ * HW];           // K then Kn
__device__ float g_mean[CO];
__device__ float g_invstd[CO];
__device__ float g_ksum[BB * CQ];
__device__ float g_vsum[BB * CO];
__device__ float g_matrix[BB * CQ * CO];
// pre-split weights (bf16 hi/lo)
__device__ __nv_bfloat16 g_wc_h[CO * CIN], g_wc_l[CO * CIN];
__device__ __nv_bfloat16 g_wq_h[384 * CO], g_wq_l[384 * CO];   // rows 320..383 zero

__device__ __forceinline__ float fixnum(float r) {
    if (isnan(r)) return 0.0f;
    if (isinf(r)) return r > 0.0f ? 1.0f : -1.0f;
    return r;
}

__device__ __forceinline__ uint32_t smem_u32(const void* p) {
    uint32_t a;
    asm("{ .reg .u64 t; cvta.to.shared.u64 t, %1; cvt.u32.u64 %0, t; }"
        : "=r"(a) : "l"(p));
    return a;
}

#define CP_ASYNC(dst, src) \
    asm volatile("cp.async.cg.shared.global [%0], [%1], 16;" :: "r"(dst), "l"(src))
#define CP_COMMIT() asm volatile("cp.async.commit_group;" ::: "memory")
#define CP_WAIT0()  asm volatile("cp.async.wait_group 0;" ::: "memory")

__device__ __forceinline__ void ldm_x4(uint32_t& r0, uint32_t& r1,
                                       uint32_t& r2, uint32_t& r3, uint32_t addr) {
    asm volatile("ldmatrix.sync.aligned.m8n8.x4.shared.b16 {%0,%1,%2,%3}, [%4];"
                 : "=r"(r0), "=r"(r1), "=r"(r2), "=r"(r3) : "r"(addr));
}
__device__ __forceinline__ void ldm_x4t(uint32_t& r0, uint32_t& r1,
                                        uint32_t& r2, uint32_t& r3, uint32_t addr) {
    asm volatile("ldmatrix.sync.aligned.m8n8.x4.trans.shared.b16 {%0,%1,%2,%3}, [%4];"
                 : "=r"(r0), "=r"(r1), "=r"(r2), "=r"(r3) : "r"(addr));
}

// hi/lo bf16 split of two floats, packed as bf16x2 (x -> low 16 bits)
__device__ __forceinline__ void split_pack(float x, float y, uint32_t& h, uint32_t& l) {
    __nv_bfloat162 hb = __floats2bfloat162_rn(x, y);
    h = *reinterpret_cast<uint32_t*>(&hb);
    float rx = x - __bfloat162float(hb.x);
    float ry = y - __bfloat162float(hb.y);
    __nv_bfloat162 lb = __floats2bfloat162_rn(rx, ry);
    l = *reinterpret_cast<uint32_t*>(&lb);
}

// m16n8k16 row.col bf16 MMA, f32 accumulate in-place
__device__ __forceinline__ void mma16816(float* c,
    uint32_t a0, uint32_t a1, uint32_t a2, uint32_t a3,
    uint32_t b0, uint32_t b1)
{
    asm volatile(
        "mma.sync.aligned.m16n8k16.row.col.f32.bf16.bf16.f32 "
        "{%0,%1,%2,%3}, {%4,%5,%6,%7}, {%8,%9}, {%0,%1,%2,%3};"
        : "+f"(c[0]), "+f"(c[1]), "+f"(c[2]), "+f"(c[3])
        : "r"(a0), "r"(a1), "r"(a2), "r"(a3), "r"(b0), "r"(b1));
}

// ---------------------------------------------------------------------------
__global__ void zero_kernel() {
    int tid = blockIdx.x * blockDim.x + threadIdx.x;
    int total = BB * CQ + BB * CQ * CO;
    for (int i = tid; i < total; i += gridDim.x * blockDim.x) {
        if (i < BB * CQ) g_ksum[i] = 0.0f;
        else g_matrix[i - BB * CQ] = 0.0f;
    }
}

// ---------------------------------------------------------------------------
// Pre-split all weights to bf16 hi/lo. total = 256*1024 + 384*256 = 360448 els.
__global__ __launch_bounds__(256) void convert_weights(
    const float* __restrict__ w,
    const float* __restrict__ wq, const float* __restrict__ wk,
    const float* __restrict__ wv)
{
    int idx = blockIdx.x * 256 + threadIdx.x;
    if (idx < CO * CIN) {
        float f = w[idx];
        __nv_bfloat16 h = __float2bfloat16_rn(f);
        g_wc_h[idx] = h;
        g_wc_l[idx] = __float2bfloat16_rn(f - __bfloat162float(h));
    } else {
        int j = idx - CO * CIN;
        if (j < 384 * CO) {
            int row = j >> 8, k = j & 255;
            float f = (row < 32)  ? wq[row * CO + k]
                    : (row < 64)  ? wk[(row - 32) * CO + k]
                    : (row < 320) ? wv[(row - 64) * CO + k] : 0.0f;
            __nv_bfloat16 h = __float2bfloat16_rn(f);
            g_wq_h[j] = h;
            g_wq_l[j] = __float2bfloat16_rn(f - __bfloat162float(h));
        }
    }
}

// ---------------------------------------------------------------------------
// conv 1x1: g_x[b,m,n] = sum_c w[m,c]*fcat[b,c,n]. CTA 128x128, k-chunk 32.
// 4 warps of 64x64 microtiles (high fragment reuse). 128 threads.
__global__ __launch_bounds__(128, 2) void conv_gemm_mma(
    const float* __restrict__ s5, const float* __restrict__ s4,
    const float* __restrict__ s3, const float* __restrict__ s2)
{
    extern __shared__ char smem[];
    const uint32_t sb = smem_u32(smem);

    const int t = threadIdx.x;
    const int wid = t >> 5, lane = t & 31;
    const int g = lane >> 2, tg = lane & 3;
    const int b = blockIdx.z, m0 = blockIdx.y * 128, n0 = blockIdx.x * 128;
    const int wm = (wid & 1) * 64, wn = (wid >> 1) * 64;

    uint32_t aA[4];
#pragma unroll
    for (int mt = 0; mt < 4; mt++)
        aA[mt] = sb + XSA + (uint32_t)((wm + mt * 16 + (lane & 15)) * 80 + (lane >> 4) * 16);
    uint32_t aB[4];
#pragma unroll
    for (int p = 0; p < 4; p++)
        aB[p] = sb + XSB + (uint32_t)((lane & 15) * 272 + (wn + p * 16 + (lane >> 4) * 8) * 2);

    float acc[4][8][4];
#pragma unroll
    for (int i = 0; i < 4; i++)
#pragma unroll
        for (int j = 0; j < 8; j++)
#pragma unroll
            for (int r = 0; r < 4; r++) acc[i][j][r] = 0.0f;

    auto issue = [&](int buf, int k0) {
#pragma unroll
        for (int i = 0; i < 8; i++) {        // A bf16: 1024 x 16B chunks
            int id = t + i * 128;
            int half = id >> 9, id2 = id & 511, row = id2 >> 2, cs = id2 & 3;
            const __nv_bfloat16* src = (half ? g_wc_l : g_wc_h)
                + (size_t)(m0 + row) * CIN + k0 + cs * 8;
            CP_ASYNC(sb + XSA + buf * XSA_BUF + half * XSA_HALF + row * 80 + cs * 16, src);
        }
        int blk = k0 >> 8;                    // B fp32 stage: 1024 x 16B chunks
        const float* srcp = (blk == 0 ? s5 : blk == 1 ? s4 : blk == 2 ? s3 : s2)
            + (size_t)(b * CINE + (k0 & 255)) * HW + n0;
#pragma unroll
        for (int i = 0; i < 8; i++) {
            int id = t + i * 128;
            int row = id >> 5, c = id & 31;
            CP_ASYNC(sb + XST + buf * XST_BUF + row * 512 + ((c + row) & 31) * 16,
                     srcp + (size_t)row * HW + c * 4);
        }
    };

    issue(0, 0); CP_COMMIT();
    const int NI = CIN / 32;
    for (int it = 0; it < NI; it++) {
        const int buf = it & 1;
        CP_WAIT0();
        __syncthreads();   // buf data visible to all; all prev-iter mma reads done
        if (it + 1 < NI) { issue(buf ^ 1, (it + 1) * 32); CP_COMMIT(); }

        // elementwise split B: stage[buf] -> sBh/sBl (rotated stage columns)
        {
            const int r = t & 31, q = t >> 5;     // q in 0..3, 8 cols each
            const char* stg = smem + XST + buf * XST_BUF + r * 512;
            char* ph = smem + XSB + buf * XSB_BUF + r * 272 + q * 64;
            char* pl = ph + XSB_HALF;
#pragma unroll
            for (int cc = 0; cc < 8; cc++) {
                int c = 8 * q + cc;
                float4 v = *(const float4*)(stg + ((c + r) & 31) * 16);
                uint32_t h0, l0, h1, l1;
                split_pack(v.x, v.y, h0, l0);
                split_pack(v.z, v.w, h1, l1);
                *(uint32_t*)(ph + cc * 8 + 0) = h0; *(uint32_t*)(ph + cc * 8 + 4) = h1;
                *(uint32_t*)(pl + cc * 8 + 0) = l0; *(uint32_t*)(pl + cc * 8 + 4) = l1;
            }
        }
        __syncthreads();

        const uint32_t offA = buf * XSA_BUF, offB = buf * XSB_BUF;
#pragma unroll
        for (int ks = 0; ks < 2; ks++) {
            const uint32_t oA = offA + ks * 32, oB = offB + ks * 4352;
            uint32_t af[4][4], bh[8][2], bl[8][2];
#pragma unroll
            for (int p = 0; p < 4; p++)
                ldm_x4t(bh[2 * p][0], bh[2 * p][1], bh[2 * p + 1][0], bh[2 * p + 1][1],
                        aB[p] + oB);
#pragma unroll
            for (int mt = 0; mt < 4; mt++)
                ldm_x4(af[mt][0], af[mt][1], af[mt][2], af[mt][3], aA[mt] + oA);
#pragma unroll
            for (int mt = 0; mt < 4; mt++)
#pragma unroll
                for (int nt = 0; nt < 8; nt++)
                    mma16816(acc[mt][nt], af[mt][0], af[mt][1], af[mt][2], af[mt][3],
                             bh[nt][0], bh[nt][1]);
#pragma unroll
            for (int p = 0; p < 4; p++)
                ldm_x4t(bl[2 * p][0], bl[2 * p][1], bl[2 * p + 1][0], bl[2 * p + 1][1],
                        aB[p] + oB + XSB_HALF);
#pragma unroll
            for (int mt = 0; mt < 4; mt++)
#pragma unroll
                for (int nt = 0; nt < 8; nt++)
                    mma16816(acc[mt][nt], af[mt][0], af[mt][1], af[mt][2], af[mt][3],
                             bl[nt][0], bl[nt][1]);
#pragma unroll
            for (int mt = 0; mt < 4; mt++)
                ldm_x4(af[mt][0], af[mt][1], af[mt][2], af[mt][3], aA[mt] + oA + XSA_HALF);
#pragma unroll
            for (int mt = 0; mt < 4; mt++)
#pragma unroll
                for (int nt = 0; nt < 8; nt++)
                    mma16816(acc[mt][nt], af[mt][0], af[mt][1], af[mt][2], af[mt][3],
                             bh[nt][0], bh[nt][1]);
        }
    }

    // writeback
#pragma unroll
    for (int mt = 0; mt < 4; mt++) {
        int m = m0 + wm + mt * 16 + g;
        float* base = g_x + (size_t)(b * CO + m) * HW + n0 + wn + 2 * tg;
#pragma unroll
        for (int nt = 0; nt < 8; nt++) {
            float* p = base + nt * 8;
            *(float2*)p = make_float2(acc[mt][nt][0], acc[mt][nt][1]);
            *(float2*)(p + 8 * HW) = make_float2(acc[mt][nt][2], acc[mt][nt][3]);
        }
    }
}

// ---------------------------------------------------------------------------
// BN statistics over raw conv output: one block per channel
__global__ __launch_bounds__(512) void bn_stats() {
    const int co = blockIdx.x;
    const int tid = threadIdx.x;
    float s = 0.0f, ss = 0.0f;
    for (int b = 0; b < BB; b++) {
        const float* p = g_x + (size_t)(b * CO + co) * HW;
        for (int i = tid; i < HW; i += 512) {
            float v = p[i];
            s += v;
            ss += v * v;
        }
    }
    __shared__ float rs[512], rss[512];
    rs[tid] = s; rss[tid] = ss;
    __syncthreads();
    for (int off = 256; off > 0; off >>= 1) {
        if (tid < off) { rs[tid] += rs[tid + off]; rss[tid] += rss[tid + off]; }
        __syncthreads();
    }
    if (tid == 0) {
        const float cnt = (float)(BB * HW);
        float mean = rs[0] / cnt;
        float var  = rss[0] / cnt - mean * mean;
        g_mean[co]   = mean;
        g_invstd[co] = rsqrtf(var + 1e-5f);
    }
}

// ---------------------------------------------------------------------------
// QKV GEMM: same pipeline, BN+ReLU fused into the elementwise split.
// rows 0..31 = Q, 32..63 = K, 64..319 = V (padded weights handle 320..383).
__global__ __launch_bounds__(128, 2) void qkv_gemm_mma(
    const float* __restrict__ bq, const float* __restrict__ bk,
    const float* __restrict__ bv,
    const float* __restrict__ bn_gamma, const float* __restrict__ bn_beta)
{
    extern __shared__ char smem[];
    const uint32_t sb = smem_u32(smem);

    const int t = threadIdx.x;
    const int wid = t >> 5, lane = t & 31;
    const int g = lane >> 2, tg = lane & 3;
    const int b = blockIdx.z, m0 = blockIdx.y * 128, n0 = blockIdx.x * 128;
    const int wm = (wid & 1) * 64, wn = (wid >> 1) * 64;

    {   // BN scale/shift (two channels per thread, 128 threads)
#pragma unroll
        for (int rr = 0; rr < 2; rr++) {
            int c = t + rr * 128;
            float sc = g_invstd[c] * bn_gamma[c];
            ((float*)(smem + XSSC))[c] = sc;
            ((float*)(smem + XSSF))[c] = bn_beta[c] - g_mean[c] * sc;
        }
    }

    uint32_t aA[4];
#pragma unroll
    for (int mt = 0; mt < 4; mt++)
        aA[mt] = sb + XSA + (uint32_t)((wm + mt * 16 + (lane & 15)) * 80 + (lane >> 4) * 16);
    uint32_t aB[4];
#pragma unroll
    for (int p = 0; p < 4; p++)
        aB[p] = sb + XSB + (uint32_t)((lane & 15) * 272 + (wn + p * 16 + (lane >> 4) * 8) * 2);

    float acc[4][8][4];
#pragma unroll
    for (int i = 0; i < 4; i++)
#pragma unroll
        for (int j = 0; j < 8; j++)
#pragma unroll
            for (int r = 0; r < 4; r++) acc[i][j][r] = 0.0f;

    auto issue = [&](int buf, int k0) {
#pragma unroll
        for (int i = 0; i < 8; i++) {
            int id = t + i * 128;
            int half = id >> 9, id2 = id & 511, row = id2 >> 2, cs = id2 & 3;
            const __nv_bfloat16* src = (half ? g_wq_l : g_wq_h)
                + (size_t)(m0 + row) * CO + k0 + cs * 8;
            CP_ASYNC(sb + XSA + buf * XSA_BUF + half * XSA_HALF + row * 80 + cs * 16, src);
        }
        const float* srcp = g_x + (size_t)(b * CO + k0) * HW + n0;
#pragma unroll
        for (int i = 0; i < 8; i++) {
            int id = t + i * 128;
            int row = id >> 5, c = id & 31;
            CP_ASYNC(sb + XST + buf * XST_BUF + row * 512 + ((c + row) & 31) * 16,
                     srcp + (size_t)row * HW + c * 4);
        }
    };

    issue(0, 0); CP_COMMIT();
    const int NI = CO / 32;
    for (int it = 0; it < NI; it++) {
        const int buf = it & 1;
        CP_WAIT0();
        __syncthreads();   // buf data visible; all prev-iter mma reads done
        if (it + 1 < NI) { issue(buf ^ 1, (it + 1) * 32); CP_COMMIT(); }

        {   // BN + ReLU + split
            const int r = t & 31, q = t >> 5;
            const int ch = it * 32 + r;
            const float sc = ((const float*)(smem + XSSC))[ch];
            const float sf = ((const float*)(smem + XSSF))[ch];
            const char* stg = smem + XST + buf * XST_BUF + r * 512;
            char* ph = smem + XSB + buf * XSB_BUF + r * 272 + q * 64;
            char* pl = ph + XSB_HALF;
#pragma unroll
            for (int cc = 0; cc < 8; cc++) {
                int c = 8 * q + cc;
                float4 v = *(const float4*)(stg + ((c + r) & 31) * 16);
                v.x = fmaxf(v.x * sc + sf, 0.0f);
                v.y = fmaxf(v.y * sc + sf, 0.0f);
                v.z = fmaxf(v.z * sc + sf, 0.0f);
                v.w = fmaxf(v.w * sc + sf, 0.0f);
                uint32_t h0, l0, h1, l1;
                split_pack(v.x, v.y, h0, l0);
                split_pack(v.z, v.w, h1, l1);
                *(uint32_t*)(ph + cc * 8 + 0) = h0; *(uint32_t*)(ph + cc * 8 + 4) = h1;
                *(uint32_t*)(pl + cc * 8 + 0) = l0; *(uint32_t*)(pl + cc * 8 + 4) = l1;
            }
        }
        __syncthreads();

        const uint32_t offA = buf * XSA_BUF, offB = buf * XSB_BUF;
#pragma unroll
        for (int ks = 0; ks < 2; ks++) {
            const uint32_t oA = offA + ks * 32, oB = offB + ks * 4352;
            uint32_t af[4][4], bh[8][2], bl[8][2];
#pragma unroll
            for (int p = 0; p < 4; p++)
                ldm_x4t(bh[2 * p][0], bh[2 * p][1], bh[2 * p + 1][0], bh[2 * p + 1][1],
                        aB[p] + oB);
#pragma unroll
            for (int mt = 0; mt < 4; mt++)
                ldm_x4(af[mt][0], af[mt][1], af[mt][2], af[mt][3], aA[mt] + oA);
#pragma unroll
            for (int mt = 0; mt < 4; mt++)
#pragma unroll
                for (int nt = 0; nt < 8; nt++)
                    mma16816(acc[mt][nt], af[mt][0], af[mt][1], af[mt][2], af[mt][3],
                             bh[nt][0], bh[nt][1]);
#pragma unroll
            for (int p = 0; p < 4; p++)
                ldm_x4t(bl[2 * p][0], bl[2 * p][1], bl[2 * p + 1][0], bl[2 * p + 1][1],
                        aB[p] + oB + XSB_HALF);
#pragma unroll
            for (int mt = 0; mt < 4; mt++)
#pragma unroll
                for (int nt = 0; nt < 8; nt++)
                    mma16816(acc[mt][nt], af[mt][0], af[mt][1], af[mt][2], af[mt][3],
                             bl[nt][0], bl[nt][1]);
#pragma unroll
            for (int mt = 0; mt < 4; mt++)
                ldm_x4(af[mt][0], af[mt][1], af[mt][2], af[mt][3], aA[mt] + oA + XSA_HALF);
#pragma unroll
            for (int mt = 0; mt < 4; mt++)
#pragma unroll
                for (int nt = 0; nt < 8; nt++)
                    mma16816(acc[mt][nt], af[mt][0], af[mt][1], af[mt][2], af[mt][3],
                             bh[nt][0], bh[nt][1]);
        }
    }

    // writeback with bias + routing (rows mg and mg+8)
#pragma unroll
    for (int mt = 0; mt < 4; mt++) {
#pragma unroll
        for (int half = 0; half < 2; half++) {
            int mg = m0 + wm + mt * 16 + g + half * 8;
            if (mg >= 320) continue;
            float bias; float* dst;
            if (mg < 32)      { bias = bq[mg];      dst = g_q + (size_t)(b * CQ + mg) * HW; }
            else if (mg < 64) { bias = bk[mg - 32]; dst = g_k + (size_t)(b * CQ + mg - 32) * HW; }
            else              { bias = bv[mg - 64]; dst = g_v + (size_t)(b * CO + mg - 64) * HW; }
            dst += n0 + wn + 2 * tg;
#pragma unroll
            for (int nt = 0; nt < 8; nt++)
                *(float2*)(dst + nt * 8) = make_float2(acc[mt][nt][2 * half] + bias,
                                                       acc[mt][nt][2 * half + 1] + bias);
        }
    }
}

// ---------------------------------------------------------------------------
// L2-normalize Q and K over channels per position, accumulate Ksum
__global__ __launch_bounds__(256) void normalize_qk() {
    const int b = blockIdx.y;
    const int n = blockIdx.x * 256 + threadIdx.x;
    const int lane = threadIdx.x & 31;

    {
        float q[CQ];
        float s = 0.0f;
#pragma unroll
        for (int c = 0; c < CQ; c++) {
            q[c] = g_q[(size_t)(b * CQ + c) * HW + n];
            s += q[c] * q[c];
        }
        float sc = 1.0f / fmaxf(sqrtf(s), 1e-6f);
#pragma unroll
        for (int c = 0; c < CQ; c++)
            g_q[(size_t)(b * CQ + c) * HW + n] = q[c] * sc;
    }
    {
        float k[CQ];
        float s = 0.0f;
#pragma unroll
        for (int c = 0; c < CQ; c++) {
            k[c] = g_k[(size_t)(b * CQ + c) * HW + n];
            s += k[c] * k[c];
        }
        float sc = 1.0f / fmaxf(sqrtf(s), 1e-6f);
#pragma unroll
        for (int c = 0; c < CQ; c++) {
            float v = k[c] * sc;
            g_k[(size_t)(b * CQ + c) * HW + n] = v;
            float r = v;
#pragma unroll
            for (int off = 16; off > 0; off >>= 1)
                r += __shfl_down_sync(0xffffffffu, r, off);
            if (lane == 0) atomicAdd(&g_ksum[b * CQ + c], r);
        }
    }
}

// ---------------------------------------------------------------------------
__global__ __launch_bounds__(256) void vsum_kernel() {
    const int c = blockIdx.x;
    const int b = blockIdx.y;
    const int tid = threadIdx.x;
    const float* p = g_v + (size_t)(b * CO + c) * HW;
    float s = 0.0f;
    for (int i = tid; i < HW; i += 256) s += p[i];
    __shared__ float rs[256];
    rs[tid] = s;
    __syncthreads();
    for (int off = 128; off > 0; off >>= 1) {
        if (tid < off) rs[tid] += rs[tid + off];
        __syncthreads();
    }
    if (tid == 0) g_vsum[b * CO + c] = rs[0];
}

// ---------------------------------------------------------------------------
// matrix[b,q,c] = sum_n Kn[b,q,n] * V[b,c,n]  (split-K over n, atomic reduce)
__global__ __launch_bounds__(256) void matrix_kernel() {
    const int b   = blockIdx.z;
    const int c0  = blockIdx.y * 64;
    const int nb0 = blockIdx.x * 512;

    __shared__ float sK[CQ][65];
    __shared__ float sV[64][65];

    const int t  = threadIdx.x;
    const int c  = t & 63;
    const int qg = t >> 6;

    float acc[8];
#pragma unroll
    for (int i = 0; i < 8; i++) acc[i] = 0.0f;

    for (int nb = nb0; nb < nb0 + 512; nb += 64) {
#pragma unroll
        for (int i = 0; i < 8; i++) {
            int idx = t + i * 256;
            int q = idx >> 6, j = idx & 63;
            sK[q][j] = g_k[(size_t)(b * CQ + q) * HW + nb + j];
        }
#pragma unroll
        for (int i = 0; i < 16; i++) {
            int idx = t + i * 256;
            int cc = idx >> 6, j = idx & 63;
            sV[cc][j] = g_v[(size_t)(b * CO + c0 + cc) * HW + nb + j];
        }
        __syncthreads();
#pragma unroll 8
        for (int j = 0; j < 64; j++) {
            float vv = sV[c][j];
#pragma unroll
            for (int i = 0; i < 8; i++)
                acc[i] += sK[qg * 8 + i][j] * vv;
        }
        __syncthreads();
    }
#pragma unroll
    for (int i = 0; i < 8; i++)
        atomicAdd(&g_matrix[(size_t)(b * CQ + qg * 8 + i) * CO + c0 + c], acc[i]);
}

// ---------------------------------------------------------------------------
// Final: out = nan_to_num(gamma * (Vsum + Qn^T matrix) * tailor) + feat
// feat = relu(bn(g_x)) computed inline.
__global__ __launch_bounds__(128) void final_kernel(
    const float* __restrict__ gamma_p,
    const float* __restrict__ bn_gamma, const float* __restrict__ bn_beta,
    float* __restrict__ out)
{
    const int b = blockIdx.y;
    const int n = blockIdx.x * 128 + threadIdx.x;
    const int tid = threadIdx.x;

    __shared__ float sM[CQ][CO];   // 32 KB
    __shared__ float sVs[CO];
    __shared__ float sKs[CQ];
    __shared__ float sScale[CO];
    __shared__ float sShift[CO];

#pragma unroll
    for (int i = 0; i < 64; i++) {
        int idx = tid + i * 128;
        ((float*)sM)[idx] = g_matrix[(size_t)b * CQ * CO + idx];
    }
#pragma unroll
    for (int r = 0; r < 2; r++) {
        int c = tid + r * 128;
        sVs[c] = g_vsum[b * CO + c];
        float scale = g_invstd[c] * bn_gamma[c];
        sScale[c] = scale;
        sShift[c] = bn_beta[c] - g_mean[c] * scale;
    }
    if (tid < CQ) sKs[tid] = g_ksum[b * CQ + tid];
    __syncthreads();

    float qn[CQ];
    float e = 0.0f;
#pragma unroll
    for (int q = 0; q < CQ; q++) {
        qn[q] = g_q[(size_t)(b * CQ + q) * HW + n];
        e += qn[q] * sKs[q];
    }
    const float tailor = 1.0f / fmaxf(NPOS + e, 1e-6f);
    const float gm = *gamma_p;

    for (int c0 = 0; c0 < CO; c0 += 4) {
        float4 a = *(const float4*)&sVs[c0];
#pragma unroll
        for (int q = 0; q < CQ; q++) {
            float4 m4 = *(const float4*)&sM[q][c0];
            a.x += qn[q] * m4.x;
            a.y += qn[q] * m4.y;
            a.z += qn[q] * m4.z;
            a.w += qn[q] * m4.w;
        }
        float r0 = fixnum(gm * a.x * tailor);
        float r1 = fixnum(gm * a.y * tailor);
        float r2 = fixnum(gm * a.z * tailor);
        float r3 = fixnum(gm * a.w * tailor);
        size_t base = (size_t)(b * CO + c0) * HW + n;
        float f0 = fmaxf(g_x[base + 0 * HW] * sScale[c0 + 0] + sShift[c0 + 0], 0.0f);
        float f1 = fmaxf(g_x[base + 1 * HW] * sScale[c0 + 1] + sShift[c0 + 1], 0.0f);
        float f2 = fmaxf(g_x[base + 2 * HW] * sScale[c0 + 2] + sShift[c0 + 2], 0.0f);
        float f3 = fmaxf(g_x[base + 3 * HW] * sScale[c0 + 3] + sShift[c0 + 3], 0.0f);
        out[base + 0 * HW] = r0 + f0;
        out[base + 1 * HW] = r1 + f1;
        out[base + 2 * HW] = r2 + f2;
        out[base + 3 * HW] = r3 + f3;
    }
}

// ---------------------------------------------------------------------------
extern "C" void kernel_launch(void* const* d_in, const int* in_sizes, int n_in,
                              void* d_out, int out_size)
{
    const float* s5 = (const float*)d_in[0];
    const float* s4 = (const float*)d_in[1];
    const float* s3 = (const float*)d_in[2];
    const float* s2 = (const float*)d_in[3];
    const float* w_conv   = (const float*)d_in[4];
    const float* bn_gamma = (const float*)d_in[5];
    const float* bn_beta  = (const float*)d_in[6];
    const float* wq = (const float*)d_in[7];
    const float* bq = (const float*)d_in[8];
    const float* wk = (const float*)d_in[9];
    const float* bk = (const float*)d_in[10];
    const float* wv = (const float*)d_in[11];
    const float* bv = (const float*)d_in[12];
    const float* gamma = (const float*)d_in[13];
    float* out = (float*)d_out;

    static int attr_done = 0;
    if (!attr_done) {
        cudaFuncSetAttribute(conv_gemm_mma, cudaFuncAttributeMaxDynamicSharedMemorySize, XTOT_QKV);
        cudaFuncSetAttribute(qkv_gemm_mma,  cudaFuncAttributeMaxDynamicSharedMemorySize, XTOT_QKV);
        attr_done = 1;
    }

    zero_kernel<<<64, 256>>>();
    convert_weights<<<1408, 256>>>(w_conv, wq, wk, wv);
    conv_gemm_mma<<<dim3(HW / 128, 2, BB), 128, XTOT_CONV>>>(s5, s4, s3, s2);
    bn_stats<<<CO, 512>>>();
    qkv_gemm_mma<<<dim3(HW / 128, 3, BB), 128, XTOT_QKV>>>(bq, bk, bv, bn_gamma, bn_beta);
    normalize_qk<<<dim3(HW / 256, BB), 256>>>();
    vsum_kernel<<<dim3(CO, BB), 256>>>();
    matrix_kernel<<<dim3(32, CO / 64, BB), 256>>>();
    final_kernel<<<dim3(HW / 128, BB), 128>>>(gamma, bn_gamma, bn_beta, out);
}